// round 1
// baseline (speedup 1.0000x reference)
#include <cuda_runtime.h>
#include <math.h>

#define NN 20000
#define EE 340000

// ---------------- device scratch (static; no allocations) ----------------
__device__ float g_QT[2048], g_KnT[2048], g_KcT[2048], g_HID[2048], g_NF[2048];
__device__ float g_C1[2048], g_C2[2048], g_C3[512];
__device__ float g_TBL[52 * 128];          // rows 0..15 VnT, 16..31 A1, 32..47 A2, 48..51 A3
__device__ float g_Lne[256], g_Lself[16], g_Uv[16];
__device__ unsigned char g_ncode[NN];
__device__ unsigned char g_ecarr[EE];
__device__ unsigned int  g_pcode[EE];      // kc | ec<<4 | erc<<8 | sc<<12
__device__ int           g_cnt16[NN * 16];
__device__ int           g_hist[NN * 36];  // [0..15] ec, [16..31] erc, [32..35] sc
__device__ unsigned int  g_selmask[NN];    // bits 0..15: kc bins, bit 16: self slot
__device__ float         g_invcnt[NN];
__device__ float         g_AGG[NN * 128];

// ---------------- pass 0: zero counters, node/edge binary codes ----------------
__global__ void k_prep(const int* __restrict__ node_states,
                       const int* __restrict__ edge_states) {
    int i = blockIdx.x * blockDim.x + threadIdx.x;
    int stride = gridDim.x * blockDim.x;
    for (; i < NN * 36; i += stride) {
        g_hist[i] = 0;
        if (i < NN * 16) g_cnt16[i] = 0;
        if (i < NN) {
            int4 s = *(const int4*)(node_states + 4 * i);
            g_ncode[i] = (unsigned char)(s.x + 2 * s.y + 4 * s.z + 8 * s.w);
        }
        if (i < EE) {
            int4 s = *(const int4*)(edge_states + 4 * i);
            g_ecarr[i] = (unsigned char)(s.x + 2 * s.y + 4 * s.z + 8 * s.w);
        }
    }
}

// ---------------- pass 1: LUT stage 1 (one block = one 128-wide table row) ----------------
__global__ void k_tab1(const float* __restrict__ emb_v, const float* __restrict__ emb_b,
                       const float* __restrict__ emb_e, const float* __restrict__ emb_s,
                       const float* __restrict__ Wq, const float* __restrict__ Wk,
                       const float* __restrict__ Wv, const float* __restrict__ Wek,
                       const float* __restrict__ Wcf, const float* __restrict__ gW1,
                       const float* __restrict__ gb1) {
    __shared__ float r1[128], r2[128];
    int b = blockIdx.x, j = threadIdx.x;
    float acc = 0.f;
    if (b < 16) {                                   // QT + NF
        r1[j] = emb_v[2 * b * 128 + j]; __syncthreads();
        for (int k = 0; k < 128; k++) acc += r1[k] * Wq[k * 128 + j];
        g_QT[b * 128 + j] = acc;
        g_NF[b * 128 + j] = r1[j];
    } else if (b < 32) {                            // KnT
        int c = b - 16;
        r1[j] = emb_v[2 * c * 128 + j]; __syncthreads();
        for (int k = 0; k < 128; k++) acc += r1[k] * Wk[k * 128 + j];
        g_KnT[c * 128 + j] = acc;
    } else if (b < 48) {                            // VnT -> TBL rows 0..15
        int c = b - 32;
        r1[j] = emb_v[2 * c * 128 + j]; __syncthreads();
        for (int k = 0; k < 128; k++) acc += r1[k] * Wv[k * 128 + j];
        g_TBL[c * 128 + j] = acc;
    } else if (b < 64) {                            // KcT = Kn + emb_b@Wek
        int c = b - 48;
        r1[j] = emb_v[2 * c * 128 + j];
        r2[j] = emb_b[2 * c * 128 + j]; __syncthreads();
        for (int k = 0; k < 128; k++)
            acc += r1[k] * Wk[k * 128 + j] + r2[k] * Wek[k * 128 + j];
        g_KcT[c * 128 + j] = acc;
    } else if (b < 80) {                            // C1 = emb_e @ Wcf[0:128]
        int c = b - 64;
        r1[j] = emb_e[c * 128 + j]; __syncthreads();
        for (int k = 0; k < 128; k++) acc += r1[k] * Wcf[k * 128 + j];
        g_C1[c * 128 + j] = acc;
    } else if (b < 96) {                            // C2 = emb_e @ Wcf[128:256]
        int c = b - 80;
        r1[j] = emb_e[c * 128 + j]; __syncthreads();
        for (int k = 0; k < 128; k++) acc += r1[k] * Wcf[(128 + k) * 128 + j];
        g_C2[c * 128 + j] = acc;
    } else if (b < 100) {                           // C3 = emb_s @ Wcf[256:384]
        int c = b - 96;
        r1[j] = emb_s[c * 128 + j]; __syncthreads();
        for (int k = 0; k < 128; k++) acc += r1[k] * Wcf[(256 + k) * 128 + j];
        g_C3[c * 128 + j] = acc;
    } else {                                        // HID = relu(NF@gW1+gb1)
        int c = b - 100;
        r1[j] = emb_v[2 * c * 128 + j]; __syncthreads();
        for (int k = 0; k < 128; k++) acc += r1[k] * gW1[k * 128 + j];
        acc += gb1[j];
        g_HID[c * 128 + j] = acc > 0.f ? acc : 0.f;
    }
}

// ---------------- pass 2: LUT stage 2 (A tables, logit LUT, u) ----------------
__global__ void k_tab2(const float* __restrict__ Wev, const float* __restrict__ gW2,
                       const float* __restrict__ gb2) {
    int b = blockIdx.x, j = threadIdx.x;
    if (b < 36) {
        __shared__ float row[128];
        const float* src = (b < 16) ? &g_C1[b * 128]
                         : (b < 32) ? &g_C2[(b - 16) * 128]
                                    : &g_C3[(b - 32) * 128];
        row[j] = src[j]; __syncthreads();
        float acc = 0.f;
        for (int k = 0; k < 128; k++) acc += row[k] * Wev[k * 128 + j];
        g_TBL[(16 + b) * 128 + j] = acc;            // rows 16..51
    } else {
        const float sq = sqrtf(128.0f);
        for (int job = j; job < 256; job += 128) {
            int q = job >> 4, k = job & 15;
            float acc = 0.f;
            for (int i = 0; i < 128; i++) acc += g_QT[q * 128 + i] * g_KcT[k * 128 + i];
            g_Lne[job] = acc / sq;
        }
        if (j < 16) {
            float acc = 0.f;
            for (int i = 0; i < 128; i++) acc += g_QT[j * 128 + i] * g_KnT[j * 128 + i];
            g_Lself[j] = acc / sq;
            float a2 = 0.f;
            for (int i = 0; i < 128; i++) a2 += g_HID[j * 128 + i] * gW2[i];
            a2 += gb2[0];
            g_Uv[j] = 1.f / (1.f + expf(-a2));
        }
    }
}

// ---------------- pass 3: per-edge code pack + kc histogram ----------------
__global__ void k_edge0(const int* __restrict__ src_idx, const int* __restrict__ dst_idx,
                        const int* __restrict__ rev_idx, const int* __restrict__ sl_idx,
                        const float* __restrict__ scalars) {
    int e = blockIdx.x * blockDim.x + threadIdx.x;
    if (e >= EE) return;
    int s = src_idx[e], d = dst_idx[e];
    int kc  = g_ncode[s];
    int ec  = g_ecarr[e];
    int erc = g_ecarr[rev_idx[e]];
    float s0   = scalars[e];
    float recv = scalars[sl_idx[d]];
    float send = scalars[sl_idx[s]];
    int rlx  = (s0 < recv) ? 1 : 0;
    int rlxd = ((send + s0) < recv) ? 1 : 0;
    int sc = rlx + 2 * rlxd;
    g_pcode[e] = (unsigned)kc | ((unsigned)ec << 4) | ((unsigned)erc << 8) | ((unsigned)sc << 12);
    atomicAdd(&g_cnt16[d * 16 + kc], 1);
}

// ---------------- pass 4: per-node attention on the weighted multiset ----------------
__global__ void k_att() {
    int n = blockIdx.x * blockDim.x + threadIdx.x;
    if (n >= NN) return;
    int q = g_ncode[n];
    float vals[17]; int wts[17]; int ids[17];
    vals[0] = g_Lself[q]; wts[0] = 1; ids[0] = 16;
    int M = 1;
    for (int c = 0; c < 16; c++) {
        int w = g_cnt16[n * 16 + c];
        if (w > 0) { vals[M] = g_Lne[q * 16 + c]; wts[M] = w; ids[M] = c; M++; }
    }
    // insertion sort descending
    for (int i = 1; i < M; i++) {
        float v = vals[i]; int w = wts[i], id = ids[i]; int j = i - 1;
        while (j >= 0 && vals[j] < v) {
            vals[j + 1] = vals[j]; wts[j + 1] = wts[j]; ids[j + 1] = ids[j]; j--;
        }
        vals[j + 1] = v; wts[j + 1] = w; ids[j + 1] = id;
    }
    float maxv = vals[0];
    float sumexp = 0.f;
    for (int i = 0; i < M; i++) sumexp += (float)wts[i] * expf(vals[i] - maxv);
    // expanded-position pass (faithful to reference support counting)
    float S = 0.f, S2 = 0.f; int k = 0, k15 = 0, ksp = 0;
    for (int i = 0; i < M; i++) {
        float z = vals[i], z2 = z * z;
        for (int r = 0; r < wts[i]; r++) {
            k++; S += z; S2 += z2;
            float fk = (float)k;
            float mz = S / fk, mz2 = S2 / fk;
            float dd = mz * mz - mz2 + 1.f / fk; if (dd < 0.f) dd = 0.f;
            float tc = mz - sqrtf(dd);
            if (z > tc) k15++;
            if (fk * z > S - 1.f) ksp++;
        }
    }
    float tau15 = 0.f, tausp = 0.f;
    S = 0.f; S2 = 0.f; k = 0;
    int kmax = k15 > ksp ? k15 : ksp;
    for (int i = 0; i < M && k < kmax; i++) {
        float z = vals[i], z2 = z * z;
        for (int r = 0; r < wts[i] && k < kmax; r++) {
            k++; S += z; S2 += z2;
            if (k == k15) {
                float fk = (float)k;
                float mz = S / fk, mz2 = S2 / fk;
                float dd = mz * mz - mz2 + 1.f / fk; if (dd < 0.f) dd = 0.f;
                tau15 = mz - sqrtf(dd);
            }
            if (k == ksp) tausp = (S - 1.f) / (float)ksp;
        }
    }
    float u = g_Uv[q];
    float wl = u * 2.f, wh = (u - 0.5f) * 2.f;
    bool low = (u <= 0.5f);
    unsigned mask = 0; int cs = 0;
    for (int i = 0; i < M; i++) {
        float v = vals[i];
        float psoft = expf(v - maxv) / sumexp;
        float r15 = v - tau15; if (r15 < 0.f) r15 = 0.f;
        float p15 = r15 * r15;
        float rsp = v - tausp; if (rsp < 0.f) rsp = 0.f;
        float prob = low ? (1.f - wl) * psoft + wl * p15
                         : (1.f - wh) * p15 + wh * rsp;
        if (prob > 1e-6f) { mask |= (1u << ids[i]); cs += wts[i]; }
    }
    g_selmask[n] = mask;
    g_invcnt[n] = 1.f / ((float)cs + 1e-9f);
}

// ---------------- pass 5: conditional per-edge histograms (selected edges only) ----------------
__global__ void k_hist(const int* __restrict__ dst_idx) {
    int e = blockIdx.x * blockDim.x + threadIdx.x;
    if (e >= EE) return;
    int d = dst_idx[e];
    unsigned p = g_pcode[e];
    unsigned m = g_selmask[d];
    if ((m >> (p & 15u)) & 1u) {
        atomicAdd(&g_hist[d * 36 + ((p >> 4) & 15u)], 1);
        atomicAdd(&g_hist[d * 36 + 16 + ((p >> 8) & 15u)], 1);
        atomicAdd(&g_hist[d * 36 + 32 + ((p >> 12) & 3u)], 1);
    }
}

// ---------------- pass 6: per-node agg (52-row weighted sum) + node_out ----------------
__global__ void k_nodeout(float* __restrict__ out_node) {
    __shared__ float T[52 * 128];
    __shared__ float NFs[16 * 128];
    __shared__ float w[52];
    int t = threadIdx.x;
    for (int i = t; i < 52 * 128; i += 128) T[i] = g_TBL[i];
    for (int i = t; i < 16 * 128; i += 128) NFs[i] = g_NF[i];
    __syncthreads();
    int n0 = blockIdx.x * 32;
    for (int ni = 0; ni < 32; ni++) {
        int n = n0 + ni;
        if (n >= NN) break;
        unsigned mask = g_selmask[n];
        int q = g_ncode[n];
        if (t < 52) {
            float wv;
            if (t < 16) {
                wv = ((mask >> t) & 1u) ? (float)g_cnt16[n * 16 + t] : 0.f;
                if (t == q && ((mask >> 16) & 1u)) wv += 1.f;   // self slot uses Vn[q]
            } else {
                wv = (float)g_hist[n * 36 + (t - 16)];
            }
            w[t] = wv;
        }
        __syncthreads();
        float acc = 0.f;
        #pragma unroll
        for (int i = 0; i < 52; i++) acc += w[i] * T[i * 128 + t];
        acc *= g_invcnt[n];
        out_node[n * 128 + t] = NFs[q * 128 + t] + acc;
        g_AGG[n * 128 + t] = acc;
        __syncthreads();
    }
}

// ---------------- pass 7: edge_out broadcast (the big stream) ----------------
__global__ void k_edgeout(const float* __restrict__ emb_e, const int* __restrict__ dst_idx,
                          float* __restrict__ out_edge) {
    __shared__ float EF[16 * 128];
    int t = threadIdx.x;
    for (int i = t; i < 2048; i += 256) EF[i] = emb_e[i];
    __syncthreads();
    int warp = t >> 5, lane = t & 31;
    int ebase = (blockIdx.x * 8 + warp) * 8;
    for (int i = 0; i < 8; i++) {
        int e = ebase + i;
        if (e >= EE) break;
        int d = dst_idx[e];
        int ec = (g_pcode[e] >> 4) & 15;
        float4 a = *(const float4*)(g_AGG + (size_t)d * 128 + lane * 4);
        float4 f = *(const float4*)(EF + ec * 128 + lane * 4);
        float4 o = make_float4(a.x + f.x, a.y + f.y, a.z + f.z, a.w + f.w);
        *(float4*)(out_edge + (size_t)e * 128 + lane * 4) = o;
    }
}

// ---------------- host ----------------
extern "C" void kernel_launch(void* const* d_in, const int* in_sizes, int n_in,
                              void* d_out, int out_size) {
    const int*   node_states = (const int*)d_in[0];
    const int*   edge_states = (const int*)d_in[1];
    const float* scalars     = (const float*)d_in[2];
    const int*   src_idx     = (const int*)d_in[3];
    const int*   dst_idx     = (const int*)d_in[4];
    const int*   rev_idx     = (const int*)d_in[5];
    const int*   sl_idx      = (const int*)d_in[7];
    int wb = (n_in >= 23) ? 9 : 8;   // skip max_deg scalar if present
    const float* emb_v = (const float*)d_in[wb + 0];
    const float* emb_b = (const float*)d_in[wb + 1];
    const float* emb_e = (const float*)d_in[wb + 2];
    const float* emb_s = (const float*)d_in[wb + 3];
    const float* Wq    = (const float*)d_in[wb + 4];
    const float* Wk    = (const float*)d_in[wb + 5];
    const float* Wv    = (const float*)d_in[wb + 6];
    const float* Wek   = (const float*)d_in[wb + 7];
    const float* Wev   = (const float*)d_in[wb + 8];
    const float* Wcf   = (const float*)d_in[wb + 9];
    const float* gW1   = (const float*)d_in[wb + 10];
    const float* gb1   = (const float*)d_in[wb + 11];
    const float* gW2   = (const float*)d_in[wb + 12];
    const float* gb2   = (const float*)d_in[wb + 13];
    (void)in_sizes; (void)out_size;

    float* out_node = (float*)d_out;
    float* out_edge = out_node + (size_t)NN * 128;

    k_prep   <<<(NN * 36 + 255) / 256, 256>>>(node_states, edge_states);
    k_tab1   <<<116, 128>>>(emb_v, emb_b, emb_e, emb_s, Wq, Wk, Wv, Wek, Wcf, gW1, gb1);
    k_tab2   <<<37, 128>>>(Wev, gW2, gb2);
    k_edge0  <<<(EE + 255) / 256, 256>>>(src_idx, dst_idx, rev_idx, sl_idx, scalars);
    k_att    <<<(NN + 255) / 256, 256>>>();
    k_hist   <<<(EE + 255) / 256, 256>>>(dst_idx);
    k_nodeout<<<(NN + 31) / 32, 128>>>(out_node);
    k_edgeout<<<(EE + 63) / 64, 256>>>(emb_e, dst_idx, out_edge);
}

// round 2
// speedup vs baseline: 1.3013x; 1.3013x over previous
#include <cuda_runtime.h>
#include <math.h>

#define NN 20000
#define EE 340000

// ---------------- device scratch (static; no allocations) ----------------
__device__ float g_QT[2048], g_KnT[2048], g_KcT[2048], g_HID[2048], g_NF[2048];
__device__ float g_C1[2048], g_C2[2048], g_C3[512];
__device__ float g_TBL[52 * 128];          // rows 0..15 VnT, 16..31 A1, 32..47 A2, 48..51 A3
__device__ float g_Lne[256], g_Lself[16], g_Uv[16];
__device__ unsigned char g_ncode[NN];
__device__ unsigned char g_ecarr[EE];
__device__ unsigned int  g_pcode[EE];      // kc | ec<<4 | erc<<8 | sc<<12
__device__ int           g_cnt16[NN * 16];
__device__ int           g_hist[NN * 36];  // [0..15] ec, [16..31] erc, [32..35] sc
__device__ unsigned int  g_selmask[NN];    // bits 0..15: kc bins, bit 16: self slot
__device__ float         g_invcnt[NN];
__device__ float         g_AGG[NN * 128];

// ---------------- pass 0: node/edge binary codes ----------------
__global__ void k_codes(const int* __restrict__ node_states,
                        const int* __restrict__ edge_states) {
    int i = blockIdx.x * blockDim.x + threadIdx.x;
    if (i < NN) {
        int4 s = *(const int4*)(node_states + 4 * i);
        g_ncode[i] = (unsigned char)(s.x + 2 * s.y + 4 * s.z + 8 * s.w);
    }
    if (i < EE) {
        int4 s = *(const int4*)(edge_states + 4 * i);
        g_ecarr[i] = (unsigned char)(s.x + 2 * s.y + 4 * s.z + 8 * s.w);
    }
}

// ---------------- pass 1: LUT stage 1 (one block = one 128-wide table row) ----------------
__global__ void k_tab1(const float* __restrict__ emb_v, const float* __restrict__ emb_b,
                       const float* __restrict__ emb_e, const float* __restrict__ emb_s,
                       const float* __restrict__ Wq, const float* __restrict__ Wk,
                       const float* __restrict__ Wv, const float* __restrict__ Wek,
                       const float* __restrict__ Wcf, const float* __restrict__ gW1,
                       const float* __restrict__ gb1) {
    __shared__ float r1[128], r2[128];
    int b = blockIdx.x, j = threadIdx.x;
    float acc = 0.f;
    if (b < 16) {                                   // QT + NF
        r1[j] = emb_v[2 * b * 128 + j]; __syncthreads();
        #pragma unroll 8
        for (int k = 0; k < 128; k++) acc += r1[k] * Wq[k * 128 + j];
        g_QT[b * 128 + j] = acc;
        g_NF[b * 128 + j] = r1[j];
    } else if (b < 32) {                            // KnT
        int c = b - 16;
        r1[j] = emb_v[2 * c * 128 + j]; __syncthreads();
        #pragma unroll 8
        for (int k = 0; k < 128; k++) acc += r1[k] * Wk[k * 128 + j];
        g_KnT[c * 128 + j] = acc;
    } else if (b < 48) {                            // VnT -> TBL rows 0..15
        int c = b - 32;
        r1[j] = emb_v[2 * c * 128 + j]; __syncthreads();
        #pragma unroll 8
        for (int k = 0; k < 128; k++) acc += r1[k] * Wv[k * 128 + j];
        g_TBL[c * 128 + j] = acc;
    } else if (b < 64) {                            // KcT = Kn + emb_b@Wek
        int c = b - 48;
        r1[j] = emb_v[2 * c * 128 + j];
        r2[j] = emb_b[2 * c * 128 + j]; __syncthreads();
        #pragma unroll 8
        for (int k = 0; k < 128; k++)
            acc += r1[k] * Wk[k * 128 + j] + r2[k] * Wek[k * 128 + j];
        g_KcT[c * 128 + j] = acc;
    } else if (b < 80) {                            // C1 = emb_e @ Wcf[0:128]
        int c = b - 64;
        r1[j] = emb_e[c * 128 + j]; __syncthreads();
        #pragma unroll 8
        for (int k = 0; k < 128; k++) acc += r1[k] * Wcf[k * 128 + j];
        g_C1[c * 128 + j] = acc;
    } else if (b < 96) {                            // C2 = emb_e @ Wcf[128:256]
        int c = b - 80;
        r1[j] = emb_e[c * 128 + j]; __syncthreads();
        #pragma unroll 8
        for (int k = 0; k < 128; k++) acc += r1[k] * Wcf[(128 + k) * 128 + j];
        g_C2[c * 128 + j] = acc;
    } else if (b < 100) {                           // C3 = emb_s @ Wcf[256:384]
        int c = b - 96;
        r1[j] = emb_s[c * 128 + j]; __syncthreads();
        #pragma unroll 8
        for (int k = 0; k < 128; k++) acc += r1[k] * Wcf[(256 + k) * 128 + j];
        g_C3[c * 128 + j] = acc;
    } else {                                        // HID = relu(NF@gW1+gb1)
        int c = b - 100;
        r1[j] = emb_v[2 * c * 128 + j]; __syncthreads();
        #pragma unroll 8
        for (int k = 0; k < 128; k++) acc += r1[k] * gW1[k * 128 + j];
        acc += gb1[j];
        g_HID[c * 128 + j] = acc > 0.f ? acc : 0.f;
    }
}

// ---------------- pass 2: LUT stage 2 (A tables, logit LUT, u) ----------------
__global__ void k_tab2(const float* __restrict__ Wev, const float* __restrict__ gW2,
                       const float* __restrict__ gb2) {
    int b = blockIdx.x, j = threadIdx.x;
    if (b < 36) {
        __shared__ float row[128];
        const float* src = (b < 16) ? &g_C1[b * 128]
                         : (b < 32) ? &g_C2[(b - 16) * 128]
                                    : &g_C3[(b - 32) * 128];
        row[j] = src[j]; __syncthreads();
        float acc = 0.f;
        #pragma unroll 8
        for (int k = 0; k < 128; k++) acc += row[k] * Wev[k * 128 + j];
        g_TBL[(16 + b) * 128 + j] = acc;            // rows 16..51
    } else {
        const float sq = sqrtf(128.0f);
        for (int job = j; job < 256; job += 128) {
            int q = job >> 4, k = job & 15;
            float acc = 0.f;
            #pragma unroll 8
            for (int i = 0; i < 128; i++) acc += g_QT[q * 128 + i] * g_KcT[k * 128 + i];
            g_Lne[job] = acc / sq;
        }
        if (j < 16) {
            float acc = 0.f;
            #pragma unroll 8
            for (int i = 0; i < 128; i++) acc += g_QT[j * 128 + i] * g_KnT[j * 128 + i];
            g_Lself[j] = acc / sq;
            float a2 = 0.f;
            #pragma unroll 8
            for (int i = 0; i < 128; i++) a2 += g_HID[j * 128 + i] * gW2[i];
            a2 += gb2[0];
            g_Uv[j] = 1.f / (1.f + expf(-a2));
        }
    }
}

// ---------------- pass 3: per-edge code pack + kc histogram (4 edges/thread) ----------------
__global__ void k_edge0(const int* __restrict__ src_idx, const int* __restrict__ dst_idx,
                        const int* __restrict__ rev_idx, const int* __restrict__ sl_idx,
                        const float* __restrict__ scalars) {
    int e0 = (blockIdx.x * blockDim.x + threadIdx.x) * 4;
    if (e0 >= EE) return;
    int4 s4 = *(const int4*)(src_idx + e0);
    int4 d4 = *(const int4*)(dst_idx + e0);
    int4 r4 = *(const int4*)(rev_idx + e0);
    float4 sc4 = *(const float4*)(scalars + e0);
    #pragma unroll
    for (int i = 0; i < 4; i++) {
        int e = e0 + i;
        int s = (i == 0) ? s4.x : (i == 1) ? s4.y : (i == 2) ? s4.z : s4.w;
        int d = (i == 0) ? d4.x : (i == 1) ? d4.y : (i == 2) ? d4.z : d4.w;
        int rv = (i == 0) ? r4.x : (i == 1) ? r4.y : (i == 2) ? r4.z : r4.w;
        float s0 = (i == 0) ? sc4.x : (i == 1) ? sc4.y : (i == 2) ? sc4.z : sc4.w;
        int kc  = g_ncode[s];
        int ec  = g_ecarr[e];
        int erc = g_ecarr[rv];
        float recv = scalars[sl_idx[d]];
        float send = scalars[sl_idx[s]];
        int rlx  = (s0 < recv) ? 1 : 0;
        int rlxd = ((send + s0) < recv) ? 1 : 0;
        int sc = rlx + 2 * rlxd;
        g_pcode[e] = (unsigned)kc | ((unsigned)ec << 4) | ((unsigned)erc << 8) | ((unsigned)sc << 12);
        atomicAdd(&g_cnt16[d * 16 + kc], 1);
    }
}

// ---------------- pass 4: per-node attention, sort-free, register-resident ----------------
__global__ void k_att() {
    int n = blockIdx.x * blockDim.x + threadIdx.x;
    if (n >= NN) return;
    int q = g_ncode[n];

    float z[17]; int wi[17];
    {
        const int4* c4 = (const int4*)(g_cnt16 + n * 16);
        #pragma unroll
        for (int v = 0; v < 4; v++) {
            int4 c = c4[v];
            wi[v * 4 + 0] = c.x; wi[v * 4 + 1] = c.y;
            wi[v * 4 + 2] = c.z; wi[v * 4 + 3] = c.w;
        }
    }
    #pragma unroll
    for (int c = 0; c < 16; c++) z[c] = g_Lne[q * 16 + c];
    z[16] = g_Lself[q]; wi[16] = 1;

    // max + softmax denominator over expanded multiset
    float maxv = -1e30f;
    #pragma unroll
    for (int i = 0; i < 17; i++) if (wi[i] > 0 && z[i] > maxv) maxv = z[i];
    float sumexp = 0.f;
    #pragma unroll
    for (int i = 0; i < 17; i++) sumexp += (float)wi[i] * expf(z[i] - maxv);

    // order-free prefix stats + expanded support scan
    int k15 = 0, ksp = 0, best15 = 0, bestsp = 0;
    float tau15 = 0.f, tausp = 0.f;
    #pragma unroll
    for (int g = 0; g < 17; g++) {
        int wg = wi[g];
        if (wg <= 0) continue;
        float zg = z[g];
        float Wb = 0.f, Sb = 0.f, S2b = 0.f;
        #pragma unroll
        for (int h = 0; h < 17; h++) {
            bool before = (wi[h] > 0) && ((z[h] > zg) || (z[h] == zg && h < g));
            if (before) {
                float wh = (float)wi[h];
                Wb += wh; Sb += wh * z[h]; S2b += wh * z[h] * z[h];
            }
        }
        float S = Sb, S2 = S2b;
        int kk = (int)Wb;
        float zg2 = zg * zg;
        for (int r = 0; r < wg; r++) {
            kk++; S += zg; S2 += zg2;
            float fk = (float)kk;
            float mz = S / fk, mz2 = S2 / fk;
            float dd = mz * mz - mz2 + 1.f / fk; if (dd < 0.f) dd = 0.f;
            float tc = mz - sqrtf(dd);
            if (zg > tc) {
                k15++;
                if (kk > best15) { best15 = kk; tau15 = tc; }
            }
            if (fk * zg > S - 1.f) {
                ksp++;
                if (kk > bestsp) { bestsp = kk; tausp = (S - 1.f) / fk; }
            }
        }
    }

    float u = g_Uv[q];
    float wl = u * 2.f, wh_ = (u - 0.5f) * 2.f;
    bool low = (u <= 0.5f);
    unsigned mask = 0; int cs = 0;
    #pragma unroll
    for (int i = 0; i < 17; i++) {
        if (wi[i] <= 0) continue;
        float v = z[i];
        float psoft = expf(v - maxv) / sumexp;
        float r15 = v - tau15; if (r15 < 0.f) r15 = 0.f;
        float p15 = r15 * r15;
        float rsp = v - tausp; if (rsp < 0.f) rsp = 0.f;
        float prob = low ? (1.f - wl) * psoft + wl * p15
                         : (1.f - wh_) * p15 + wh_ * rsp;
        if (prob > 1e-6f) { mask |= (1u << i); cs += wi[i]; }
    }
    g_selmask[n] = mask;
    g_invcnt[n] = 1.f / ((float)cs + 1e-9f);
}

// ---------------- pass 5: conditional per-edge histograms ----------------
__global__ void k_hist(const int* __restrict__ dst_idx) {
    int e = blockIdx.x * blockDim.x + threadIdx.x;
    if (e >= EE) return;
    int d = __ldg(dst_idx + e);
    unsigned p = g_pcode[e];
    unsigned m = g_selmask[d];
    if ((m >> (p & 15u)) & 1u) {
        atomicAdd(&g_hist[d * 36 + ((p >> 4) & 15u)], 1);
        atomicAdd(&g_hist[d * 36 + 16 + ((p >> 8) & 15u)], 1);
        atomicAdd(&g_hist[d * 36 + 32 + ((p >> 12) & 3u)], 1);
    }
}

// ---------------- pass 6: per-node agg (tables in registers) + node_out ----------------
__global__ void k_nodeout(float* __restrict__ out_node) {
    __shared__ float NFs[16 * 128];
    __shared__ float wsh[2][52];
    int t = threadIdx.x;
    float Tr[52];
    #pragma unroll
    for (int i = 0; i < 52; i++) Tr[i] = g_TBL[i * 128 + t];
    for (int i = t; i < 2048; i += 128) NFs[i] = g_NF[i];
    __syncthreads();
    int n0 = blockIdx.x * 16;
    #pragma unroll 1
    for (int ni = 0; ni < 16; ni++) {
        int n = n0 + ni;
        if (n >= NN) break;
        float* wb = wsh[ni & 1];
        unsigned mask = g_selmask[n];
        int q = g_ncode[n];
        if (t < 52) {
            float wv;
            if (t < 16) {
                wv = ((mask >> t) & 1u) ? (float)g_cnt16[n * 16 + t] : 0.f;
                if (t == q && ((mask >> 16) & 1u)) wv += 1.f;   // self slot uses Vn[q]
            } else {
                wv = (float)g_hist[n * 36 + (t - 16)];
            }
            wb[t] = wv;
        }
        __syncthreads();
        float acc = 0.f;
        #pragma unroll
        for (int i = 0; i < 52; i++) acc += wb[i] * Tr[i];
        acc *= g_invcnt[n];
        out_node[n * 128 + t] = NFs[q * 128 + t] + acc;
        g_AGG[n * 128 + t] = acc;
    }
}

// ---------------- pass 7: edge_out broadcast (the big stream) ----------------
__global__ void k_edgeout(const float* __restrict__ emb_e, const int* __restrict__ dst_idx,
                          float* __restrict__ out_edge) {
    __shared__ float EF[16 * 128];
    int t = threadIdx.x;
    for (int i = t; i < 2048; i += 256) EF[i] = emb_e[i];
    __syncthreads();
    int warp = t >> 5, lane = t & 31;
    int ebase = (blockIdx.x * 8 + warp) * 16;
    #pragma unroll 2
    for (int i = 0; i < 16; i++) {
        int e = ebase + i;
        if (e >= EE) break;
        int d = __ldg(dst_idx + e);
        int ec = (g_pcode[e] >> 4) & 15;
        float4 a = *(const float4*)(g_AGG + (size_t)d * 128 + lane * 4);
        float4 f = *(const float4*)(EF + ec * 128 + lane * 4);
        float4 o = make_float4(a.x + f.x, a.y + f.y, a.z + f.z, a.w + f.w);
        __stcs((float4*)(out_edge + (size_t)e * 128 + lane * 4), o);
    }
}

// ---------------- host ----------------
extern "C" void kernel_launch(void* const* d_in, const int* in_sizes, int n_in,
                              void* d_out, int out_size) {
    const int*   node_states = (const int*)d_in[0];
    const int*   edge_states = (const int*)d_in[1];
    const float* scalars     = (const float*)d_in[2];
    const int*   src_idx     = (const int*)d_in[3];
    const int*   dst_idx     = (const int*)d_in[4];
    const int*   rev_idx     = (const int*)d_in[5];
    const int*   sl_idx      = (const int*)d_in[7];
    int wb = (n_in >= 23) ? 9 : 8;   // skip max_deg scalar if present
    const float* emb_v = (const float*)d_in[wb + 0];
    const float* emb_b = (const float*)d_in[wb + 1];
    const float* emb_e = (const float*)d_in[wb + 2];
    const float* emb_s = (const float*)d_in[wb + 3];
    const float* Wq    = (const float*)d_in[wb + 4];
    const float* Wk    = (const float*)d_in[wb + 5];
    const float* Wv    = (const float*)d_in[wb + 6];
    const float* Wek   = (const float*)d_in[wb + 7];
    const float* Wev   = (const float*)d_in[wb + 8];
    const float* Wcf   = (const float*)d_in[wb + 9];
    const float* gW1   = (const float*)d_in[wb + 10];
    const float* gb1   = (const float*)d_in[wb + 11];
    const float* gW2   = (const float*)d_in[wb + 12];
    const float* gb2   = (const float*)d_in[wb + 13];
    (void)in_sizes; (void)out_size;

    float* out_node = (float*)d_out;
    float* out_edge = out_node + (size_t)NN * 128;

    void* p_cnt16 = nullptr; void* p_hist = nullptr;
    cudaGetSymbolAddress(&p_cnt16, g_cnt16);
    cudaGetSymbolAddress(&p_hist,  g_hist);
    cudaMemsetAsync(p_cnt16, 0, sizeof(int) * NN * 16, 0);
    cudaMemsetAsync(p_hist,  0, sizeof(int) * NN * 36, 0);

    k_codes  <<<(EE + 255) / 256, 256>>>(node_states, edge_states);
    k_tab1   <<<116, 128>>>(emb_v, emb_b, emb_e, emb_s, Wq, Wk, Wv, Wek, Wcf, gW1, gb1);
    k_tab2   <<<37, 128>>>(Wev, gW2, gb2);
    k_edge0  <<<(EE / 4 + 255) / 256, 256>>>(src_idx, dst_idx, rev_idx, sl_idx, scalars);
    k_att    <<<(NN + 255) / 256, 256>>>();
    k_hist   <<<(EE + 255) / 256, 256>>>(dst_idx);
    k_nodeout<<<(NN + 15) / 16, 128>>>(out_node);
    k_edgeout<<<(EE + 127) / 128, 256>>>(emb_e, dst_idx, out_edge);
}